// round 2
// baseline (speedup 1.0000x reference)
#include <cuda_runtime.h>
#include <cstddef>

// Problem constants
#define T_STEPS 4
#define BATCH   8
#define C_DIM   384
#define H_DIM   1536
#define N_SP    784
#define NH      8
#define HD      48          // C/NH
#define TB      (T_STEPS*BATCH)   // 32

// Scratch (device globals -- no allocation allowed)
__device__ float g_buf1[(size_t)T_STEPS*BATCH*H_DIM*N_SP]; // 38.5M el, generic pre-activation buffer
__device__ float g_q  [(size_t)T_STEPS*BATCH*C_DIM*N_SP];
__device__ float g_k  [(size_t)T_STEPS*BATCH*C_DIM*N_SP];
__device__ float g_v  [(size_t)T_STEPS*BATCH*C_DIM*N_SP];
__device__ float g_m  [(size_t)TB*NH*HD*HD];               // per (t,b,h) 48x48 K^T V
__device__ float g_epi[2*H_DIM];                           // per-channel inv / off

// ---------------------------------------------------------------------------
// BN-fold precompute: inv = gamma/sqrt(var+eps); off = (bias-mean)*inv + beta
// bnp layout: [4,C] rows gamma,beta,mean,var
__global__ void prep_epi_kernel(const float* __restrict__ bnp,
                                const float* __restrict__ bias,
                                float* __restrict__ epi, int C) {
    int c = blockIdx.x * blockDim.x + threadIdx.x;
    if (c >= C) return;
    float gamma = bnp[c];
    float beta  = bnp[C + c];
    float mean  = bnp[2*C + c];
    float var   = bnp[3*C + c];
    float inv = gamma / sqrtf(var + 1e-5f);
    float b = bias ? bias[c] : 0.0f;
    epi[c]     = inv;
    epi[C + c] = (b - mean) * inv + beta;
}

// ---------------------------------------------------------------------------
// Batched GEMM + fused BN: Y[z,o,n] = (sum_c W[o,c] X[z,c,n]) * inv[o] + off[o]
// z = t*B+b (grid.z), tiles 128x128x16, 256 thr, 8x8 microtile.
__global__ __launch_bounds__(256) void gemm_bn_kernel(
    const float* __restrict__ X, const float* __restrict__ W,
    const float* __restrict__ epi, float* __restrict__ Y,
    int Cin, int Cout)
{
    __shared__ float Ws[16][128];
    __shared__ float Xs[16][132];

    const int tb = blockIdx.z;
    const int m0 = blockIdx.y * 128;
    const int n0 = blockIdx.x * 128;
    const int tid = threadIdx.x;

    const float* Xb = X + (size_t)tb * Cin * N_SP;

    float acc[8][8];
    #pragma unroll
    for (int i = 0; i < 8; i++)
        #pragma unroll
        for (int j = 0; j < 8; j++) acc[i][j] = 0.0f;

    const int wm = tid >> 1;          // 0..127 (output row in tile)
    const int wc = (tid & 1) * 8;     // 0 or 8 (k offset)

    for (int c0 = 0; c0 < Cin; c0 += 16) {
        // W tile load: 128 rows x 16 k, transposed into Ws[k][m]
        {
            const float* wp = W + (size_t)(m0 + wm) * Cin + c0 + wc;
            float4 w0 = *(const float4*)wp;
            float4 w1 = *(const float4*)(wp + 4);
            Ws[wc+0][wm] = w0.x; Ws[wc+1][wm] = w0.y;
            Ws[wc+2][wm] = w0.z; Ws[wc+3][wm] = w0.w;
            Ws[wc+4][wm] = w1.x; Ws[wc+5][wm] = w1.y;
            Ws[wc+6][wm] = w1.z; Ws[wc+7][wm] = w1.w;
        }
        // X tile load: 16 k x 128 n
        #pragma unroll
        for (int r = 0; r < 2; r++) {
            int l  = tid + r * 256;       // 0..511
            int k  = l >> 5;              // 0..15
            int n4 = (l & 31) * 4;        // 0..124
            int n  = n0 + n4;
            float4 xv;
            if (n < N_SP) {               // N_SP%4==0 and n%4==0 -> full vec valid
                xv = *(const float4*)(Xb + (size_t)(c0 + k) * N_SP + n);
            } else {
                xv.x = xv.y = xv.z = xv.w = 0.0f;
            }
            *(float4*)&Xs[k][n4] = xv;
        }
        __syncthreads();

        const int mf = (tid >> 4) * 8;
        const int nf = (tid & 15) * 8;
        #pragma unroll
        for (int kk = 0; kk < 16; kk++) {
            float4 a0 = *(const float4*)&Ws[kk][mf];
            float4 a1 = *(const float4*)&Ws[kk][mf + 4];
            float4 b0 = *(const float4*)&Xs[kk][nf];
            float4 b1 = *(const float4*)&Xs[kk][nf + 4];
            float a[8] = {a0.x,a0.y,a0.z,a0.w,a1.x,a1.y,a1.z,a1.w};
            float b[8] = {b0.x,b0.y,b0.z,b0.w,b1.x,b1.y,b1.z,b1.w};
            #pragma unroll
            for (int i = 0; i < 8; i++)
                #pragma unroll
                for (int j = 0; j < 8; j++)
                    acc[i][j] += a[i] * b[j];
        }
        __syncthreads();
    }

    const int mf = (tid >> 4) * 8;
    const int nf = (tid & 15) * 8;
    #pragma unroll
    for (int i = 0; i < 8; i++) {
        int o = m0 + mf + i;
        float inv = epi[o];
        float off = epi[Cout + o];
        float* yp = Y + ((size_t)tb * Cout + o) * N_SP;
        #pragma unroll
        for (int j = 0; j < 8; j++) {
            int n = n0 + nf + j;
            if (n < N_SP) yp[n] = acc[i][j] * inv + off;
        }
    }
}

// ---------------------------------------------------------------------------
// LIF over T=4 (tau=2, hard reset), optional residual added to spike output.
// ept = B*CH*N (elements per timestep). Matches jax rounding: v += (x-v)*0.5
__global__ void lif_kernel(const float* __restrict__ pre,
                           const float* __restrict__ res,
                           float* __restrict__ out,
                           int ept, float vth)
{
    int i = blockIdx.x * blockDim.x + threadIdx.x;
    if (i >= ept) return;
    float v = 0.0f;
    if (res) {
        #pragma unroll
        for (int t = 0; t < T_STEPS; t++) {
            float x = pre[i + (size_t)t * ept];
            v = __fadd_rn(v, __fmul_rn(__fsub_rn(x, v), 0.5f));
            float s = (v >= vth) ? 1.0f : 0.0f;
            out[i + (size_t)t * ept] = s + res[i + (size_t)t * ept];
            if (s != 0.0f) v = 0.0f;
        }
    } else {
        #pragma unroll
        for (int t = 0; t < T_STEPS; t++) {
            float x = pre[i + (size_t)t * ept];
            v = __fadd_rn(v, __fmul_rn(__fsub_rn(x, v), 0.5f));
            float s = (v >= vth) ? 1.0f : 0.0f;
            out[i + (size_t)t * ept] = s;
            if (s != 0.0f) v = 0.0f;
        }
    }
}

// ---------------------------------------------------------------------------
// Attention part 1: M[tb,h] = K_spk^T V_spk  (48x48, exact integers)
// One block per (tb,h). zz = tb*8 + h.
__global__ __launch_bounds__(256) void attn_m_kernel(
    const float* __restrict__ K, const float* __restrict__ V,
    float* __restrict__ M)
{
    __shared__ float Ks[HD][65];
    __shared__ float Vs[HD][65];
    const int zz = blockIdx.x;
    const int h = zz & 7;
    const int tb = zz >> 3;
    const int tid = threadIdx.x;
    const float* Kb = K + ((size_t)tb * C_DIM + h * HD) * N_SP;
    const float* Vb = V + ((size_t)tb * C_DIM + h * HD) * N_SP;

    float acc[9];
    #pragma unroll
    for (int i = 0; i < 9; i++) acc[i] = 0.0f;

    for (int n0 = 0; n0 < N_SP; n0 += 64) {
        #pragma unroll
        for (int i = 0; i < 12; i++) {          // 48*64 = 3072 = 12*256
            int l = tid + i * 256;
            int d = l >> 6;
            int nn = l & 63;
            int n = n0 + nn;
            float kv = 0.0f, vv = 0.0f;
            if (n < N_SP) {
                kv = Kb[(size_t)d * N_SP + n];
                vv = Vb[(size_t)d * N_SP + n];
            }
            Ks[d][nn] = kv;
            Vs[d][nn] = vv;
        }
        __syncthreads();
        #pragma unroll
        for (int i = 0; i < 9; i++) {           // 48*48 = 2304 = 9*256
            int p = tid + i * 256;
            int d = p / HD;
            int e = p % HD;
            float s = acc[i];
            #pragma unroll
            for (int nn = 0; nn < 64; nn++) s += Ks[d][nn] * Vs[e][nn];
            acc[i] = s;
        }
        __syncthreads();
    }
    #pragma unroll
    for (int i = 0; i < 9; i++) {
        int p = tid + i * 256;
        M[(size_t)zz * (HD*HD) + p] = acc[i];
    }
}

// Attention part 2: O[c=h*48+e, n] = 0.25 * sum_d Q_spk[h*48+d, n] * M[d,e]
__global__ __launch_bounds__(256) void attn_o_kernel(
    const float* __restrict__ Q, const float* __restrict__ M,
    float* __restrict__ O)
{
    __shared__ float Ms[HD*HD];
    const int zz = blockIdx.x;
    const int h = zz & 7;
    const int tb = zz >> 3;
    const int tid = threadIdx.x;
    for (int i = tid; i < HD*HD; i += 256) Ms[i] = M[(size_t)zz * (HD*HD) + i];
    __syncthreads();

    const float* Qb = Q + ((size_t)tb * C_DIM + h * HD) * N_SP;
    float* Ob = O + ((size_t)tb * C_DIM + h * HD) * N_SP;

    for (int rep = 0; rep < 4; rep++) {
        int n = tid + rep * 256;
        if (n < N_SP) {
            float qr[HD];
            #pragma unroll
            for (int d = 0; d < HD; d++) qr[d] = Qb[(size_t)d * N_SP + n];
            #pragma unroll 4
            for (int e = 0; e < HD; e++) {
                float s = 0.0f;
                #pragma unroll
                for (int d = 0; d < HD; d++) s += qr[d] * Ms[d * HD + e];
                Ob[(size_t)e * N_SP + n] = s * 0.25f;
            }
        }
    }
}

// ---------------------------------------------------------------------------
extern "C" void kernel_launch(void* const* d_in, const int* in_sizes, int n_in,
                              void* d_out, int out_size) {
    const float* x      = (const float*)d_in[0];
    const float* q_w    = (const float*)d_in[1];
    const float* k_w    = (const float*)d_in[2];
    const float* v_w    = (const float*)d_in[3];
    const float* q_bn   = (const float*)d_in[4];
    const float* k_bn   = (const float*)d_in[5];
    const float* v_bn   = (const float*)d_in[6];
    const float* proj_w = (const float*)d_in[7];
    const float* proj_b = (const float*)d_in[8];
    const float* proj_bn= (const float*)d_in[9];
    const float* fc1_w  = (const float*)d_in[10];
    const float* fc1_b  = (const float*)d_in[11];
    const float* fc1_bn = (const float*)d_in[12];
    const float* fc2_w  = (const float*)d_in[13];
    const float* fc2_b  = (const float*)d_in[14];
    const float* fc2_bn = (const float*)d_in[15];
    float* out = (float*)d_out;

    float *buf1, *q, *k, *v, *m, *epi;
    cudaGetSymbolAddress((void**)&buf1, g_buf1);
    cudaGetSymbolAddress((void**)&q,    g_q);
    cudaGetSymbolAddress((void**)&k,    g_k);
    cudaGetSymbolAddress((void**)&v,    g_v);
    cudaGetSymbolAddress((void**)&m,    g_m);
    cudaGetSymbolAddress((void**)&epi,  g_epi);

    const int EPT   = BATCH * C_DIM * N_SP;   // per-timestep elements (C=384)
    const int EPT_H = BATCH * H_DIM * N_SP;   // per-timestep elements (H=1536)

    dim3 g384((N_SP + 127) / 128, C_DIM / 128, TB);   // 7,3,32
    dim3 gH  ((N_SP + 127) / 128, H_DIM / 128, TB);   // 7,12,32
    int lifB  = (EPT + 255) / 256;
    int lifBH = (EPT_H + 255) / 256;

    // --- q/k/v convs + BN + LIF ---
    prep_epi_kernel<<<2, 256>>>(q_bn, nullptr, epi, C_DIM);
    gemm_bn_kernel<<<g384, 256>>>(x, q_w, epi, buf1, C_DIM, C_DIM);
    lif_kernel<<<lifB, 256>>>(buf1, nullptr, q, EPT, 1.0f);

    prep_epi_kernel<<<2, 256>>>(k_bn, nullptr, epi, C_DIM);
    gemm_bn_kernel<<<g384, 256>>>(x, k_w, epi, buf1, C_DIM, C_DIM);
    lif_kernel<<<lifB, 256>>>(buf1, nullptr, k, EPT, 1.0f);

    prep_epi_kernel<<<2, 256>>>(v_bn, nullptr, epi, C_DIM);
    gemm_bn_kernel<<<g384, 256>>>(x, v_w, epi, buf1, C_DIM, C_DIM);
    lif_kernel<<<lifB, 256>>>(buf1, nullptr, v, EPT, 1.0f);

    // --- attention (reassociated: O = Q (K^T V), exact integers) ---
    attn_m_kernel<<<TB * NH, 256>>>(k, v, m);
    attn_o_kernel<<<TB * NH, 256>>>(q, m, buf1);

    // attn_lif (v_th = 0.5) -> spikes into q (reuse)
    lif_kernel<<<lifB, 256>>>(buf1, nullptr, q, EPT, 0.5f);

    // --- proj + BN + LIF + residual: x1 = x + spike -> k (reuse) ---
    prep_epi_kernel<<<2, 256>>>(proj_bn, proj_b, epi, C_DIM);
    gemm_bn_kernel<<<g384, 256>>>(q, proj_w, epi, buf1, C_DIM, C_DIM);
    lif_kernel<<<lifB, 256>>>(buf1, x, k, EPT, 1.0f);

    // --- MLP fc1 (384 -> 1536) + LIF (in-place) ---
    prep_epi_kernel<<<6, 256>>>(fc1_bn, fc1_b, epi, H_DIM);
    gemm_bn_kernel<<<gH, 256>>>(k, fc1_w, epi, buf1, C_DIM, H_DIM);
    lif_kernel<<<lifBH, 256>>>(buf1, nullptr, buf1, EPT_H, 1.0f);

    // --- MLP fc2 (1536 -> 384) + LIF + residual -> out ---
    prep_epi_kernel<<<2, 256>>>(fc2_bn, fc2_b, epi, C_DIM);
    gemm_bn_kernel<<<g384, 256>>>(buf1, fc2_w, epi, v, H_DIM, C_DIM);
    lif_kernel<<<lifB, 256>>>(v, k, out, EPT, 1.0f);
}

// round 3
// speedup vs baseline: 1.6021x; 1.6021x over previous
#include <cuda_runtime.h>
#include <cstddef>

// Problem constants
#define T_STEPS 4
#define BATCH   8
#define C_DIM   384
#define H_DIM   1536
#define N_SP    784
#define NH      8
#define HD      48          // C/NH
#define TB      (T_STEPS*BATCH)   // 32

// Scratch (device globals -- no allocation allowed)
__device__ float g_buf1[(size_t)T_STEPS*BATCH*H_DIM*N_SP]; // 38.5M el, generic pre-activation buffer
__device__ float g_q  [(size_t)T_STEPS*BATCH*C_DIM*N_SP];
__device__ float g_k  [(size_t)T_STEPS*BATCH*C_DIM*N_SP];
__device__ float g_v  [(size_t)T_STEPS*BATCH*C_DIM*N_SP];
__device__ float g_m  [(size_t)TB*NH*HD*HD];               // per (t,b,h) 48x48 K^T V
__device__ float g_epi[2*H_DIM];                           // per-channel inv / off

// ---------------------------------------------------------------------------
// BN-fold precompute: inv = gamma/sqrt(var+eps); off = (bias-mean)*inv + beta
// bnp layout: [4,C] rows gamma,beta,mean,var
__global__ void prep_epi_kernel(const float* __restrict__ bnp,
                                const float* __restrict__ bias,
                                float* __restrict__ epi, int C) {
    int c = blockIdx.x * blockDim.x + threadIdx.x;
    if (c >= C) return;
    float gamma = bnp[c];
    float beta  = bnp[C + c];
    float mean  = bnp[2*C + c];
    float var   = bnp[3*C + c];
    float inv = gamma / sqrtf(var + 1e-5f);
    float b = bias ? bias[c] : 0.0f;
    epi[c]     = inv;
    epi[C + c] = (b - mean) * inv + beta;
}

// ---------------------------------------------------------------------------
// Batched GEMM + fused BN: Y[z,o,n] = (sum_c W[o,c] X[z,c,n]) * inv[o] + off[o]
// z = t*B+b (grid.z), tiles 128x128x16, 256 thr, 8x8 microtile.
__global__ __launch_bounds__(256) void gemm_bn_kernel(
    const float* __restrict__ X, const float* __restrict__ W,
    const float* __restrict__ epi, float* __restrict__ Y,
    int Cin, int Cout)
{
    __shared__ float Ws[16][128];
    __shared__ float Xs[16][132];

    const int tb = blockIdx.z;
    const int m0 = blockIdx.y * 128;
    const int n0 = blockIdx.x * 128;
    const int tid = threadIdx.x;

    const float* Xb = X + (size_t)tb * Cin * N_SP;

    float acc[8][8];
    #pragma unroll
    for (int i = 0; i < 8; i++)
        #pragma unroll
        for (int j = 0; j < 8; j++) acc[i][j] = 0.0f;

    const int wm = tid >> 1;          // 0..127 (output row in tile)
    const int wc = (tid & 1) * 8;     // 0 or 8 (k offset)

    for (int c0 = 0; c0 < Cin; c0 += 16) {
        // W tile load: 128 rows x 16 k, transposed into Ws[k][m]
        {
            const float* wp = W + (size_t)(m0 + wm) * Cin + c0 + wc;
            float4 w0 = *(const float4*)wp;
            float4 w1 = *(const float4*)(wp + 4);
            Ws[wc+0][wm] = w0.x; Ws[wc+1][wm] = w0.y;
            Ws[wc+2][wm] = w0.z; Ws[wc+3][wm] = w0.w;
            Ws[wc+4][wm] = w1.x; Ws[wc+5][wm] = w1.y;
            Ws[wc+6][wm] = w1.z; Ws[wc+7][wm] = w1.w;
        }
        // X tile load: 16 k x 128 n
        #pragma unroll
        for (int r = 0; r < 2; r++) {
            int l  = tid + r * 256;       // 0..511
            int k  = l >> 5;              // 0..15
            int n4 = (l & 31) * 4;        // 0..124
            int n  = n0 + n4;
            float4 xv;
            if (n < N_SP) {               // N_SP%4==0 and n%4==0 -> full vec valid
                xv = *(const float4*)(Xb + (size_t)(c0 + k) * N_SP + n);
            } else {
                xv.x = xv.y = xv.z = xv.w = 0.0f;
            }
            *(float4*)&Xs[k][n4] = xv;
        }
        __syncthreads();

        const int mf = (tid >> 4) * 8;
        const int nf = (tid & 15) * 8;
        #pragma unroll
        for (int kk = 0; kk < 16; kk++) {
            float4 a0 = *(const float4*)&Ws[kk][mf];
            float4 a1 = *(const float4*)&Ws[kk][mf + 4];
            float4 b0 = *(const float4*)&Xs[kk][nf];
            float4 b1 = *(const float4*)&Xs[kk][nf + 4];
            float a[8] = {a0.x,a0.y,a0.z,a0.w,a1.x,a1.y,a1.z,a1.w};
            float b[8] = {b0.x,b0.y,b0.z,b0.w,b1.x,b1.y,b1.z,b1.w};
            #pragma unroll
            for (int i = 0; i < 8; i++)
                #pragma unroll
                for (int j = 0; j < 8; j++)
                    acc[i][j] += a[i] * b[j];
        }
        __syncthreads();
    }

    const int mf = (tid >> 4) * 8;
    const int nf = (tid & 15) * 8;
    #pragma unroll
    for (int i = 0; i < 8; i++) {
        int o = m0 + mf + i;
        float inv = epi[o];
        float off = epi[Cout + o];
        float* yp = Y + ((size_t)tb * Cout + o) * N_SP;
        #pragma unroll
        for (int j = 0; j < 8; j++) {
            int n = n0 + nf + j;
            if (n < N_SP) yp[n] = acc[i][j] * inv + off;
        }
    }
}

// ---------------------------------------------------------------------------
// LIF over T=4 (tau=2, hard reset), optional residual added to spike output.
// ept = B*CH*N (elements per timestep). Matches jax rounding: v += (x-v)*0.5
__global__ void lif_kernel(const float* __restrict__ pre,
                           const float* __restrict__ res,
                           float* __restrict__ out,
                           int ept, float vth)
{
    int i = blockIdx.x * blockDim.x + threadIdx.x;
    if (i >= ept) return;
    float v = 0.0f;
    if (res) {
        #pragma unroll
        for (int t = 0; t < T_STEPS; t++) {
            float x = pre[i + (size_t)t * ept];
            v = __fadd_rn(v, __fmul_rn(__fsub_rn(x, v), 0.5f));
            float s = (v >= vth) ? 1.0f : 0.0f;
            out[i + (size_t)t * ept] = s + res[i + (size_t)t * ept];
            if (s != 0.0f) v = 0.0f;
        }
    } else {
        #pragma unroll
        for (int t = 0; t < T_STEPS; t++) {
            float x = pre[i + (size_t)t * ept];
            v = __fadd_rn(v, __fmul_rn(__fsub_rn(x, v), 0.5f));
            float s = (v >= vth) ? 1.0f : 0.0f;
            out[i + (size_t)t * ept] = s;
            if (s != 0.0f) v = 0.0f;
        }
    }
}

// ---------------------------------------------------------------------------
// Attention part 1: M[tb,h] = K_spk^T V_spk  (48x48, exact integers)
// One block per (tb,h). zz = tb*8 + h.
__global__ __launch_bounds__(256) void attn_m_kernel(
    const float* __restrict__ K, const float* __restrict__ V,
    float* __restrict__ M)
{
    __shared__ float Ks[HD][65];
    __shared__ float Vs[HD][65];
    const int zz = blockIdx.x;
    const int h = zz & 7;
    const int tb = zz >> 3;
    const int tid = threadIdx.x;
    const float* Kb = K + ((size_t)tb * C_DIM + h * HD) * N_SP;
    const float* Vb = V + ((size_t)tb * C_DIM + h * HD) * N_SP;

    float acc[9];
    #pragma unroll
    for (int i = 0; i < 9; i++) acc[i] = 0.0f;

    for (int n0 = 0; n0 < N_SP; n0 += 64) {
        #pragma unroll
        for (int i = 0; i < 12; i++) {          // 48*64 = 3072 = 12*256
            int l = tid + i * 256;
            int d = l >> 6;
            int nn = l & 63;
            int n = n0 + nn;
            float kv = 0.0f, vv = 0.0f;
            if (n < N_SP) {
                kv = Kb[(size_t)d * N_SP + n];
                vv = Vb[(size_t)d * N_SP + n];
            }
            Ks[d][nn] = kv;
            Vs[d][nn] = vv;
        }
        __syncthreads();
        #pragma unroll
        for (int i = 0; i < 9; i++) {           // 48*48 = 2304 = 9*256
            int p = tid + i * 256;
            int d = p / HD;
            int e = p % HD;
            float s = acc[i];
            #pragma unroll
            for (int nn = 0; nn < 64; nn++) s += Ks[d][nn] * Vs[e][nn];
            acc[i] = s;
        }
        __syncthreads();
    }
    #pragma unroll
    for (int i = 0; i < 9; i++) {
        int p = tid + i * 256;
        M[(size_t)zz * (HD*HD) + p] = acc[i];
    }
}

// Attention part 2: O[c=h*48+e, n] = 0.25 * sum_d Q_spk[h*48+d, n] * M[d,e]
__global__ __launch_bounds__(256) void attn_o_kernel(
    const float* __restrict__ Q, const float* __restrict__ M,
    float* __restrict__ O)
{
    __shared__ float Ms[HD*HD];
    const int zz = blockIdx.x;
    const int h = zz & 7;
    const int tb = zz >> 3;
    const int tid = threadIdx.x;
    for (int i = tid; i < HD*HD; i += 256) Ms[i] = M[(size_t)zz * (HD*HD) + i];
    __syncthreads();

    const float* Qb = Q + ((size_t)tb * C_DIM + h * HD) * N_SP;
    float* Ob = O + ((size_t)tb * C_DIM + h * HD) * N_SP;

    for (int rep = 0; rep < 4; rep++) {
        int n = tid + rep * 256;
        if (n < N_SP) {
            float qr[HD];
            #pragma unroll
            for (int d = 0; d < HD; d++) qr[d] = Qb[(size_t)d * N_SP + n];
            #pragma unroll 4
            for (int e = 0; e < HD; e++) {
                float s = 0.0f;
                #pragma unroll
                for (int d = 0; d < HD; d++) s += qr[d] * Ms[d * HD + e];
                Ob[(size_t)e * N_SP + n] = s * 0.25f;
            }
        }
    }
}

// ---------------------------------------------------------------------------
extern "C" void kernel_launch(void* const* d_in, const int* in_sizes, int n_in,
                              void* d_out, int out_size) {
    const float* x      = (const float*)d_in[0];
    const float* q_w    = (const float*)d_in[1];
    const float* k_w    = (const float*)d_in[2];
    const float* v_w    = (const float*)d_in[3];
    const float* q_bn   = (const float*)d_in[4];
    const float* k_bn   = (const float*)d_in[5];
    const float* v_bn   = (const float*)d_in[6];
    const float* proj_w = (const float*)d_in[7];
    const float* proj_b = (const float*)d_in[8];
    const float* proj_bn= (const float*)d_in[9];
    const float* fc1_w  = (const float*)d_in[10];
    const float* fc1_b  = (const float*)d_in[11];
    const float* fc1_bn = (const float*)d_in[12];
    const float* fc2_w  = (const float*)d_in[13];
    const float* fc2_b  = (const float*)d_in[14];
    const float* fc2_bn = (const float*)d_in[15];
    float* out = (float*)d_out;

    float *buf1, *q, *k, *v, *m, *epi;
    cudaGetSymbolAddress((void**)&buf1, g_buf1);
    cudaGetSymbolAddress((void**)&q,    g_q);
    cudaGetSymbolAddress((void**)&k,    g_k);
    cudaGetSymbolAddress((void**)&v,    g_v);
    cudaGetSymbolAddress((void**)&m,    g_m);
    cudaGetSymbolAddress((void**)&epi,  g_epi);

    const int EPT   = BATCH * C_DIM * N_SP;   // per-timestep elements (C=384)
    const int EPT_H = BATCH * H_DIM * N_SP;   // per-timestep elements (H=1536)

    dim3 g384((N_SP + 127) / 128, C_DIM / 128, TB);   // 7,3,32
    dim3 gH  ((N_SP + 127) / 128, H_DIM / 128, TB);   // 7,12,32
    int lifB  = (EPT + 255) / 256;
    int lifBH = (EPT_H + 255) / 256;

    // --- q/k/v convs + BN + LIF ---
    prep_epi_kernel<<<2, 256>>>(q_bn, nullptr, epi, C_DIM);
    gemm_bn_kernel<<<g384, 256>>>(x, q_w, epi, buf1, C_DIM, C_DIM);
    lif_kernel<<<lifB, 256>>>(buf1, nullptr, q, EPT, 1.0f);

    prep_epi_kernel<<<2, 256>>>(k_bn, nullptr, epi, C_DIM);
    gemm_bn_kernel<<<g384, 256>>>(x, k_w, epi, buf1, C_DIM, C_DIM);
    lif_kernel<<<lifB, 256>>>(buf1, nullptr, k, EPT, 1.0f);

    prep_epi_kernel<<<2, 256>>>(v_bn, nullptr, epi, C_DIM);
    gemm_bn_kernel<<<g384, 256>>>(x, v_w, epi, buf1, C_DIM, C_DIM);
    lif_kernel<<<lifB, 256>>>(buf1, nullptr, v, EPT, 1.0f);

    // --- attention (reassociated: O = Q (K^T V), exact integers) ---
    attn_m_kernel<<<TB * NH, 256>>>(k, v, m);
    attn_o_kernel<<<TB * NH, 256>>>(q, m, buf1);

    // attn_lif (v_th = 0.5) -> spikes into q (reuse)
    lif_kernel<<<lifB, 256>>>(buf1, nullptr, q, EPT, 0.5f);

    // --- proj + BN + LIF + residual: x1 = x + spike -> k (reuse) ---
    prep_epi_kernel<<<2, 256>>>(proj_bn, proj_b, epi, C_DIM);
    gemm_bn_kernel<<<g384, 256>>>(q, proj_w, epi, buf1, C_DIM, C_DIM);
    lif_kernel<<<lifB, 256>>>(buf1, x, k, EPT, 1.0f);

    // --- MLP fc1 (384 -> 1536) + LIF (in-place) ---
    prep_epi_kernel<<<6, 256>>>(fc1_bn, fc1_b, epi, H_DIM);
    gemm_bn_kernel<<<gH, 256>>>(k, fc1_w, epi, buf1, C_DIM, H_DIM);
    lif_kernel<<<lifBH, 256>>>(buf1, nullptr, buf1, EPT_H, 1.0f);

    // --- MLP fc2 (1536 -> 384) + LIF + residual -> out ---
    prep_epi_kernel<<<2, 256>>>(fc2_bn, fc2_b, epi, C_DIM);
    gemm_bn_kernel<<<g384, 256>>>(buf1, fc2_w, epi, v, H_DIM, C_DIM);
    lif_kernel<<<lifB, 256>>>(v, k, out, EPT, 1.0f);
}